// round 9
// baseline (speedup 1.0000x reference)
#include <cuda_runtime.h>
#include <cuda_fp16.h>
#include <cstdint>
#include <math.h>

#define TQ 2048
#define TK 2048
#define DD 128
#define NB 16
#define BM 128
#define BN 64
#define NCH (TK/BN)
#define NTILE (TQ/BM)                  // 16
#define SEGC 8                         // chunks per key segment (512 keys)
#define NSEG (NCH/SEGC)                // 4
#define THREADS 128
#define RSTR 272
#define QSTR 272
#define QBYTES (128*QSTR)
#define BUFSZ (64*RSTR)
#define KBUF(i) (QBYTES + (i)*2*BUFSZ)
#define VBUF(i) (QBYTES + (i)*2*BUFSZ + BUFSZ)
#define SMEM_TOTAL (QBYTES + 4*BUFSZ)  // 104448

#define KVELEMS (NB*TK*DD)

__device__ __align__(16) __half KH_g[KVELEMS];
__device__ __align__(16) __half VH_g[KVELEMS];
__device__ __align__(16) float OPART_g[(size_t)NSEG*NB*NTILE*BM*DD];  // 64MB
__device__ float LPART_g[NSEG*NB*NTILE*BM];
__device__ int   PERM_g[NB*TQ];
__device__ int   SVL_g[NB*TQ];
__device__ float MV_g[NB*DD];

static __device__ __forceinline__ uint32_t smem_u32(const void* p) {
    uint32_t a;
    asm("{ .reg .u64 t; cvta.to.shared.u64 t, %1; cvt.u32.u64 %0, t; }" : "=r"(a) : "l"(p));
    return a;
}
static __device__ __forceinline__ void ldsm4(uint32_t r[4], uint32_t addr) {
    asm volatile("ldmatrix.sync.aligned.m8n8.x4.shared.b16 {%0,%1,%2,%3}, [%4];"
                 : "=r"(r[0]), "=r"(r[1]), "=r"(r[2]), "=r"(r[3]) : "r"(addr));
}
static __device__ __forceinline__ void ldsm4t(uint32_t r[4], uint32_t addr) {
    asm volatile("ldmatrix.sync.aligned.m8n8.x4.trans.shared.b16 {%0,%1,%2,%3}, [%4];"
                 : "=r"(r[0]), "=r"(r[1]), "=r"(r[2]), "=r"(r[3]) : "r"(addr));
}
static __device__ __forceinline__ void mma16816(float c[4], const uint32_t a[4],
                                                uint32_t b0, uint32_t b1) {
    asm volatile(
        "mma.sync.aligned.m16n8k16.row.col.f32.f16.f16.f32 "
        "{%0,%1,%2,%3}, {%4,%5,%6,%7}, {%8,%9}, {%0,%1,%2,%3};"
        : "+f"(c[0]), "+f"(c[1]), "+f"(c[2]), "+f"(c[3])
        : "r"(a[0]), "r"(a[1]), "r"(a[2]), "r"(a[3]), "r"(b0), "r"(b1));
}
static __device__ __forceinline__ uint32_t h2bits(float lo, float hi) {
    __half2 h = __floats2half2_rn(lo, hi);
    return *(uint32_t*)&h;
}
static __device__ __forceinline__ void cp16(uint32_t dst, const void* src) {
    asm volatile("cp.async.cg.shared.global [%0], [%1], 16;" :: "r"(dst), "l"(src) : "memory");
}
#define CP_COMMIT() asm volatile("cp.async.commit_group;" ::: "memory")
#define CP_WAIT0()  asm volatile("cp.async.wait_group 0;" ::: "memory")

// ---------------- prepass: fp32 -> fp16 for K and V ----------------
__global__ void __launch_bounds__(256)
cvt_kv(const float* __restrict__ K, const float* __restrict__ V) {
    size_t i = ((size_t)blockIdx.x * 256 + threadIdx.x) * 8;
    if (i >= KVELEMS) return;
    float4 a = *(const float4*)(K + i);
    float4 b = *(const float4*)(K + i + 4);
    uint4 w;
    w.x = h2bits(a.x, a.y); w.y = h2bits(a.z, a.w);
    w.z = h2bits(b.x, b.y); w.w = h2bits(b.z, b.w);
    *(uint4*)(KH_g + i) = w;
    a = *(const float4*)(V + i);
    b = *(const float4*)(V + i + 4);
    w.x = h2bits(a.x, a.y); w.y = h2bits(a.z, a.w);
    w.z = h2bits(b.x, b.y); w.w = h2bits(b.z, b.w);
    *(uint4*)(VH_g + i) = w;
}

// ---------------- prepass: per-batch mean of V (for vl==0 rows) ----------------
__global__ void __launch_bounds__(128)
mean_v(const float* __restrict__ Vg) {
    int b = blockIdx.x, d = threadIdx.x;
    const float* p = Vg + (size_t)b * TK * DD + d;
    float acc = 0.f;
    for (int k = 0; k < TK; k++) acc += p[(size_t)k * DD];
    MV_g[b * DD + d] = acc * (1.f / TK);
}

// ---------------- prepass: per-batch counting sort of rows by valid_len ----------------
__global__ void __launch_bounds__(256)
sort_vl(const int* __restrict__ VLg, int vstride) {
    __shared__ int hist[TK];
    __shared__ int boff[64];
    const int b = blockIdx.x, tid = threadIdx.x;
    for (int i = tid; i < TK; i += 256) hist[i] = 0;
    __syncthreads();
    for (int r = tid; r < TQ; r += 256) {
        int v = VLg[(size_t)(b * TQ + r) * vstride];
        if (v < 0) v = 0; if (v > TK - 1) v = TK - 1;
        atomicAdd(&hist[v], 1);
    }
    __syncthreads();
    if (tid < 64) {                       // block sums (64 x 32 buckets)
        int s = 0;
        #pragma unroll 4
        for (int i = 0; i < 32; i++) s += hist[tid * 32 + i];
        boff[tid] = s;
    }
    __syncthreads();
    if (tid == 0) {
        int acc = 0;
        for (int i = 0; i < 64; i++) { int t = boff[i]; boff[i] = acc; acc += t; }
    }
    __syncthreads();
    if (tid < 64) {                       // in-place exclusive offsets
        int acc = boff[tid];
        #pragma unroll 4
        for (int i = 0; i < 32; i++) {
            int t = hist[tid * 32 + i]; hist[tid * 32 + i] = acc; acc += t;
        }
    }
    __syncthreads();
    for (int r = tid; r < TQ; r += 256) {
        int v = VLg[(size_t)(b * TQ + r) * vstride];
        if (v < 0) v = 0; if (v > TK - 1) v = TK - 1;
        int pos = atomicAdd(&hist[v], 1);
        PERM_g[b * TQ + pos] = r;
        SVL_g[b * TQ + pos]  = v;
    }
}

extern __shared__ char smem[];

static __device__ __forceinline__ void issue_fill(uint32_t sK, uint32_t sV,
                                                  const __half* __restrict__ Ksrc,
                                                  const __half* __restrict__ Vsrc,
                                                  int tid) {
    #pragma unroll
    for (int i = 0; i < 8; i++) {
        int id  = i * THREADS + tid;
        int row = id >> 4, c16 = (id & 15) << 4;
        cp16(sK + row * RSTR + c16, (const char*)Ksrc + row * 256 + c16);
        cp16(sV + row * RSTR + c16, (const char*)Vsrc + row * 256 + c16);
    }
}

// ---------------- main: partial attention over one key segment ----------------
__global__ void __launch_bounds__(THREADS, 2)
attn_f16(const float* __restrict__ Qg)
{
    const int tid  = threadIdx.x;
    const int w    = tid >> 5, lane = tid & 31;
    const int g8   = lane >> 2;
    const int tig  = lane & 3;
    const int qt   = (NTILE - 1) - blockIdx.x;   // heavy tiles first
    const int b    = blockIdx.y;
    const int seg  = blockIdx.z;
    const float sc = 0.088388347648318447f;      // 1/sqrt(128)

    // segment chunk range from sorted max valid_len of this tile
    const int maxvl = SVL_g[b * TQ + qt * BM + BM - 1];
    int nch = (maxvl + 63) >> 6; if (nch > NCH) nch = NCH;
    const int c0 = seg * SEGC;
    int c1 = c0 + SEGC; if (c1 > nch) c1 = nch;
    if (c0 >= c1) return;

    const uint32_t sb = smem_u32(smem);
    const __half* KHp = KH_g + (size_t)b * TK * DD;
    const __half* VHp = VH_g + (size_t)b * TK * DD;

    issue_fill(sb + KBUF(0), sb + VBUF(0),
               KHp + (size_t)c0 * BN * DD, VHp + (size_t)c0 * BN * DD, tid);
    CP_COMMIT();

    // ---- Q tile gathered through the sort permutation (scale folded)
    const int* permt = PERM_g + b * TQ + qt * BM;
    #pragma unroll
    for (int i = 0; i < 32; i++) {
        int idx = i * THREADS + tid;
        int row = idx >> 5, c4 = (idx & 31) << 2;
        int grow = permt[row];
        float4 v = *(const float4*)(Qg + ((size_t)b * TQ + grow) * DD + c4);
        uint2 wv;
        wv.x = h2bits(v.x * sc, v.y * sc);
        wv.y = h2bits(v.z * sc, v.w * sc);
        *(uint2*)(smem + row * QSTR + c4 * 2) = wv;
    }

    // ---- valid lens for this warp's row-octets (sorted order)
    int vl[2][2];
    #pragma unroll
    for (int g = 0; g < 2; g++)
        #pragma unroll
        for (int h = 0; h < 2; h++)
            vl[g][h] = SVL_g[b * TQ + qt * BM + 32 * w + 16 * g + 8 * h + g8];

    // ---- ldmatrix lane offsets
    const int qrow = (lane & 7) + 8 * ((lane >> 3) & 1);
    const int qcol = 8 * ((lane >> 4) & 1);
    const uint32_t qwb = sb + (32 * w + qrow) * QSTR + qcol * 2;
    const int krow = ((lane >> 4) & 1) * 8 + (lane & 7);
    const int kcol = ((lane >> 3) & 1) * 8;
    const uint32_t ka_off = krow * RSTR + kcol * 2;
    const int vrow = ((lane >> 3) & 1) * 8 + (lane & 7);
    const int vcol = ((lane >> 4) & 1) * 8;
    const uint32_t va_off = vrow * RSTR + vcol * 2;

    float o0[16][4], o1[16][4];
    #pragma unroll
    for (int j = 0; j < 16; j++) {
        o0[j][0] = o0[j][1] = o0[j][2] = o0[j][3] = 0.f;
        o1[j][0] = o1[j][1] = o1[j][2] = o1[j][3] = 0.f;
    }
    float l00 = 0.f, l01 = 0.f, l10 = 0.f, l11 = 0.f;

    for (int c = c0; c < c1; c++) {
        const int cb = (c - c0) & 1;
        CP_WAIT0();
        __syncthreads();
        if (c + 1 < c1) {
            issue_fill(sb + KBUF(cb ^ 1), sb + VBUF(cb ^ 1),
                       KHp + (size_t)(c + 1) * BN * DD,
                       VHp + (size_t)(c + 1) * BN * DD, tid);
            CP_COMMIT();
        }

        // ---- S = (Q*sc) K^T  [32 rows x 64 keys per warp]
        float s0[8][4], s1[8][4];
        #pragma unroll
        for (int j = 0; j < 8; j++) {
            s0[j][0] = s0[j][1] = s0[j][2] = s0[j][3] = 0.f;
            s1[j][0] = s1[j][1] = s1[j][2] = s1[j][3] = 0.f;
        }
        const uint32_t kbase = sb + KBUF(cb) + ka_off;
        #pragma unroll
        for (int kt = 0; kt < 8; kt++) {
            uint32_t qa0[4], qa1[4];
            ldsm4(qa0, qwb + kt * 32);
            ldsm4(qa1, qwb + 16 * QSTR + kt * 32);
            #pragma unroll
            for (int jp = 0; jp < 4; jp++) {
                uint32_t kb[4];
                ldsm4(kb, kbase + jp * (16 * RSTR) + kt * 32);
                mma16816(s0[2 * jp],     qa0, kb[0], kb[1]);
                mma16816(s0[2 * jp + 1], qa0, kb[2], kb[3]);
                mma16816(s1[2 * jp],     qa1, kb[0], kb[1]);
                mma16816(s1[2 * jp + 1], qa1, kb[2], kb[3]);
            }
        }

        // ---- mask + exp (fixed max = 0); masked -> 0 (vl==0 rows handled in reduce)
        const int cbase = c * BN + 2 * tig;
        uint32_t p0h[8], p0hh[8], p1h[8], p1hh[8];
        #pragma unroll
        for (int j = 0; j < 8; j++) {
            int cc0 = cbase + 8 * j, cc1 = cc0 + 1;
            float a0 = (cc0 < vl[0][0]) ? __expf(s0[j][0]) : 0.f;
            float a1 = (cc1 < vl[0][0]) ? __expf(s0[j][1]) : 0.f;
            float a2 = (cc0 < vl[0][1]) ? __expf(s0[j][2]) : 0.f;
            float a3 = (cc1 < vl[0][1]) ? __expf(s0[j][3]) : 0.f;
            l00 += a0 + a1; l01 += a2 + a3;
            p0h[j]  = h2bits(a0, a1);
            p0hh[j] = h2bits(a2, a3);
            float b0 = (cc0 < vl[1][0]) ? __expf(s1[j][0]) : 0.f;
            float b1 = (cc1 < vl[1][0]) ? __expf(s1[j][1]) : 0.f;
            float b2 = (cc0 < vl[1][1]) ? __expf(s1[j][2]) : 0.f;
            float b3 = (cc1 < vl[1][1]) ? __expf(s1[j][3]) : 0.f;
            l10 += b0 + b1; l11 += b2 + b3;
            p1h[j]  = h2bits(b0, b1);
            p1hh[j] = h2bits(b2, b3);
        }

        // ---- O += P V
        const uint32_t vbase = sb + VBUF(cb) + va_off;
        #pragma unroll
        for (int kt = 0; kt < 4; kt++) {
            uint32_t a0[4] = { p0h[2 * kt], p0hh[2 * kt], p0h[2 * kt + 1], p0hh[2 * kt + 1] };
            uint32_t a1[4] = { p1h[2 * kt], p1hh[2 * kt], p1h[2 * kt + 1], p1hh[2 * kt + 1] };
            #pragma unroll
            for (int nb = 0; nb < 8; nb++) {
                uint32_t vb[4];
                ldsm4t(vb, vbase + kt * (16 * RSTR) + nb * 32);
                mma16816(o0[2 * nb],     a0, vb[0], vb[1]);
                mma16816(o0[2 * nb + 1], a0, vb[2], vb[3]);
                mma16816(o1[2 * nb],     a1, vb[0], vb[1]);
                mma16816(o1[2 * nb + 1], a1, vb[2], vb[3]);
            }
        }
    }

    // ---- write unnormalized partials (disjoint per (seg,b,tile) -> deterministic)
    l00 += __shfl_xor_sync(0xffffffffu, l00, 1);
    l00 += __shfl_xor_sync(0xffffffffu, l00, 2);
    l01 += __shfl_xor_sync(0xffffffffu, l01, 1);
    l01 += __shfl_xor_sync(0xffffffffu, l01, 2);
    l10 += __shfl_xor_sync(0xffffffffu, l10, 1);
    l10 += __shfl_xor_sync(0xffffffffu, l10, 2);
    l11 += __shfl_xor_sync(0xffffffffu, l11, 1);
    l11 += __shfl_xor_sync(0xffffffffu, l11, 2);

    const int tile_id = (seg * NB + b) * NTILE + qt;
    float* Pp = OPART_g + (size_t)tile_id * (BM * DD);
    float* Lp = LPART_g + tile_id * BM;
    if (tig == 0) {
        Lp[32 * w + g8]      = l00;
        Lp[32 * w + g8 + 8]  = l01;
        Lp[32 * w + 16 + g8] = l10;
        Lp[32 * w + 24 + g8] = l11;
    }
    #pragma unroll
    for (int n8 = 0; n8 < 16; n8++) {
        *(float2*)(Pp + (32 * w + g8) * DD + 8 * n8 + 2 * tig) =
            make_float2(o0[n8][0], o0[n8][1]);
        *(float2*)(Pp + (32 * w + g8 + 8) * DD + 8 * n8 + 2 * tig) =
            make_float2(o0[n8][2], o0[n8][3]);
        *(float2*)(Pp + (32 * w + 16 + g8) * DD + 8 * n8 + 2 * tig) =
            make_float2(o1[n8][0], o1[n8][1]);
        *(float2*)(Pp + (32 * w + 24 + g8) * DD + 8 * n8 + 2 * tig) =
            make_float2(o1[n8][2], o1[n8][3]);
    }
}

// ---------------- reduce partials, normalize, scatter through permutation ----------------
__global__ void __launch_bounds__(128)
reduce_o(float* __restrict__ Og) {
    const int t = blockIdx.x, b = blockIdx.y;
    const int w = threadIdx.x >> 5, lane = threadIdx.x & 31;
    const int maxvl = SVL_g[b * TQ + t * BM + BM - 1];
    int nch = (maxvl + 63) >> 6; if (nch > NCH) nch = NCH;
    const int nseg = (nch + SEGC - 1) / SEGC;

    for (int it = 0; it < 32; it++) {
        int row  = it * 4 + w;
        int svl  = SVL_g[b * TQ + t * BM + row];
        int grow = PERM_g[b * TQ + t * BM + row];
        float4 acc;
        if (svl == 0) {
            acc = *(const float4*)(MV_g + b * DD + lane * 4);
        } else {
            float l = 0.f;
            acc = make_float4(0.f, 0.f, 0.f, 0.f);
            for (int s = 0; s < nseg; s++) {
                int tile_id = (s * NB + b) * NTILE + t;
                l += LPART_g[tile_id * BM + row];
                float4 v = *(const float4*)(OPART_g + (size_t)tile_id * (BM * DD)
                                            + row * DD + lane * 4);
                acc.x += v.x; acc.y += v.y; acc.z += v.z; acc.w += v.w;
            }
            float inv = 1.f / l;
            acc.x *= inv; acc.y *= inv; acc.z *= inv; acc.w *= inv;
        }
        *(float4*)(Og + ((size_t)b * TQ + grow) * DD + lane * 4) = acc;
    }
}

extern "C" void kernel_launch(void* const* d_in, const int* in_sizes, int n_in,
                              void* d_out, int out_size) {
    const float* Q  = (const float*)d_in[0];
    const float* K  = (const float*)d_in[1];
    const float* V  = (const float*)d_in[2];
    const int*   VL = (const int*)d_in[3];

    int vstride = in_sizes[3] / (NB * TQ);   // 1 if int32 words, 2 if int64 words
    if (vstride < 1) vstride = 1;

    sort_vl<<<NB, 256>>>(VL, vstride);
    cvt_kv<<<(KVELEMS / 8 + 255) / 256, 256>>>(K, V);
    mean_v<<<NB, 128>>>(V);

    cudaFuncSetAttribute(attn_f16, cudaFuncAttributeMaxDynamicSharedMemorySize, SMEM_TOTAL);
    dim3 grid(NTILE, NB, NSEG);
    attn_f16<<<grid, THREADS, SMEM_TOTAL>>>(Q);

    reduce_o<<<dim3(NTILE, NB), 128>>>((float*)d_out);
}

// round 12
// speedup vs baseline: 1.6358x; 1.6358x over previous
#include <cuda_runtime.h>
#include <cuda_fp16.h>
#include <cstdint>
#include <math.h>

#define TQ 2048
#define TK 2048
#define DD 128
#define NB 16
#define BM 128
#define BN 64
#define NCH (TK/BN)
#define NTILE (TQ/BM)                  // 16
#define NITEM (NB*NTILE)               // 256
#define THREADS 128
#define RSTR 272
#define QSTR 272
#define QBYTES (128*QSTR)
#define BUFSZ (64*RSTR)
#define KBUF(i) (QBYTES + (i)*2*BUFSZ)
#define VBUF(i) (QBYTES + (i)*2*BUFSZ + BUFSZ)
#define SMEM_TOTAL (QBYTES + 4*BUFSZ)  // 104448 -> 2 CTAs/SM

#define KVELEMS (NB*TK*DD)

__device__ __align__(16) __half KH_g[KVELEMS];
__device__ __align__(16) __half VH_g[KVELEMS];
__device__ int PERM_g[NB*TQ];
__device__ int SVL_g[NB*TQ];           // effective vl: 0 -> 2048, else vl
__device__ int SCHED_g[NITEM];

static __device__ __forceinline__ uint32_t smem_u32(const void* p) {
    uint32_t a;
    asm("{ .reg .u64 t; cvta.to.shared.u64 t, %1; cvt.u32.u64 %0, t; }" : "=r"(a) : "l"(p));
    return a;
}
static __device__ __forceinline__ void ldsm4(uint32_t r[4], uint32_t addr) {
    asm volatile("ldmatrix.sync.aligned.m8n8.x4.shared.b16 {%0,%1,%2,%3}, [%4];"
                 : "=r"(r[0]), "=r"(r[1]), "=r"(r[2]), "=r"(r[3]) : "r"(addr));
}
static __device__ __forceinline__ void ldsm4t(uint32_t r[4], uint32_t addr) {
    asm volatile("ldmatrix.sync.aligned.m8n8.x4.trans.shared.b16 {%0,%1,%2,%3}, [%4];"
                 : "=r"(r[0]), "=r"(r[1]), "=r"(r[2]), "=r"(r[3]) : "r"(addr));
}
static __device__ __forceinline__ void mma16816(float c[4], const uint32_t a[4],
                                                uint32_t b0, uint32_t b1) {
    asm volatile(
        "mma.sync.aligned.m16n8k16.row.col.f32.f16.f16.f32 "
        "{%0,%1,%2,%3}, {%4,%5,%6,%7}, {%8,%9}, {%0,%1,%2,%3};"
        : "+f"(c[0]), "+f"(c[1]), "+f"(c[2]), "+f"(c[3])
        : "r"(a[0]), "r"(a[1]), "r"(a[2]), "r"(a[3]), "r"(b0), "r"(b1));
}
static __device__ __forceinline__ uint32_t h2bits(float lo, float hi) {
    __half2 h = __floats2half2_rn(lo, hi);
    return *(uint32_t*)&h;
}
static __device__ __forceinline__ void cp16(uint32_t dst, const void* src) {
    asm volatile("cp.async.cg.shared.global [%0], [%1], 16;" :: "r"(dst), "l"(src) : "memory");
}
#define CP_COMMIT() asm volatile("cp.async.commit_group;" ::: "memory")
#define CP_WAIT0()  asm volatile("cp.async.wait_group 0;" ::: "memory")

// ---------------- prepass: fp32 -> fp16 for K and V ----------------
__global__ void __launch_bounds__(256)
cvt_kv(const float* __restrict__ K, const float* __restrict__ V) {
    size_t i = ((size_t)blockIdx.x * 256 + threadIdx.x) * 8;
    if (i >= KVELEMS) return;
    float4 a = *(const float4*)(K + i);
    float4 b = *(const float4*)(K + i + 4);
    uint4 w;
    w.x = h2bits(a.x, a.y); w.y = h2bits(a.z, a.w);
    w.z = h2bits(b.x, b.y); w.w = h2bits(b.z, b.w);
    *(uint4*)(KH_g + i) = w;
    a = *(const float4*)(V + i);
    b = *(const float4*)(V + i + 4);
    w.x = h2bits(a.x, a.y); w.y = h2bits(a.z, a.w);
    w.z = h2bits(b.x, b.y); w.w = h2bits(b.z, b.w);
    *(uint4*)(VH_g + i) = w;
}

// ---------------- prepass: per-batch counting sort of rows by effective vl ----------------
// effective vl (evl): 0 -> 2048 (row attends uniformly to all keys), else vl. Sort key = evl-1.
__global__ void __launch_bounds__(256)
sort_vl(const int* __restrict__ VLg, int vstride) {
    __shared__ int hist[TK];
    __shared__ int boff[64];
    const int b = blockIdx.x, tid = threadIdx.x;
    for (int i = tid; i < TK; i += 256) hist[i] = 0;
    __syncthreads();
    for (int r = tid; r < TQ; r += 256) {
        int v = VLg[(size_t)(b * TQ + r) * vstride];
        if (v < 0) v = 0; if (v > TK - 1) v = TK - 1;
        int evl = (v == 0) ? TK : v;
        atomicAdd(&hist[evl - 1], 1);
    }
    __syncthreads();
    if (tid < 64) {
        int s = 0;
        #pragma unroll 4
        for (int i = 0; i < 32; i++) s += hist[tid * 32 + i];
        boff[tid] = s;
    }
    __syncthreads();
    if (tid == 0) {
        int acc = 0;
        for (int i = 0; i < 64; i++) { int t = boff[i]; boff[i] = acc; acc += t; }
    }
    __syncthreads();
    if (tid < 64) {
        int acc = boff[tid];
        #pragma unroll 4
        for (int i = 0; i < 32; i++) {
            int t = hist[tid * 32 + i]; hist[tid * 32 + i] = acc; acc += t;
        }
    }
    __syncthreads();
    for (int r = tid; r < TQ; r += 256) {
        int v = VLg[(size_t)(b * TQ + r) * vstride];
        if (v < 0) v = 0; if (v > TK - 1) v = TK - 1;
        int evl = (v == 0) ? TK : v;
        int pos = atomicAdd(&hist[evl - 1], 1);
        PERM_g[b * TQ + pos] = r;
        SVL_g[b * TQ + pos]  = evl;
    }
}

// ---------------- prepass: pairing schedule (heavy+light on the same SM) ----------------
__global__ void __launch_bounds__(NITEM)
sched_k() {
    __shared__ int cnt[33];
    __shared__ int order[NITEM];
    const int tid = threadIdx.x;
    if (tid < 33) cnt[tid] = 0;
    __syncthreads();
    const int b = tid >> 4, t = tid & 15;
    const int maxevl = SVL_g[b * TQ + t * BM + BM - 1];
    const int w = (maxevl + 63) >> 6;          // 1..32 chunks
    atomicAdd(&cnt[32 - w], 1);                // key ascending = weight descending
    __syncthreads();
    if (tid == 0) {
        int acc = 0;
        for (int i = 0; i < 33; i++) { int c = cnt[i]; cnt[i] = acc; acc += c; }
    }
    __syncthreads();
    int pos = atomicAdd(&cnt[32 - w], 1);
    order[pos] = (b << 4) | t;
    __syncthreads();
    if (tid < 148) SCHED_g[tid] = order[tid];
    else           SCHED_g[tid] = order[255 - (tid - 148)];
}

extern __shared__ char smem[];

static __device__ __forceinline__ void issue_fill(uint32_t sK, uint32_t sV,
                                                  const __half* __restrict__ Ksrc,
                                                  const __half* __restrict__ Vsrc,
                                                  int tid) {
    #pragma unroll
    for (int i = 0; i < 8; i++) {
        int id  = i * THREADS + tid;
        int row = id >> 4, c16 = (id & 15) << 4;
        cp16(sK + row * RSTR + c16, (const char*)Ksrc + row * 256 + c16);
        cp16(sV + row * RSTR + c16, (const char*)Vsrc + row * 256 + c16);
    }
}

// ---------------- main: full attention for one sorted q-tile ----------------
__global__ void __launch_bounds__(THREADS, 2)
attn_f16(const float* __restrict__ Qg, float* __restrict__ Og)
{
    const int tid  = threadIdx.x;
    const int w    = tid >> 5, lane = tid & 31;
    const int g8   = lane >> 2;
    const int tig  = lane & 3;
    const int item = SCHED_g[blockIdx.x];
    const int b    = item >> 4, qt = item & 15;
    const float sc = 0.088388347648318447f;      // 1/sqrt(128)

    const int maxevl = SVL_g[b * TQ + qt * BM + BM - 1];
    int nch = (maxevl + 63) >> 6; if (nch > NCH) nch = NCH;

    const uint32_t sb = smem_u32(smem);
    const __half* KHp = KH_g + (size_t)b * TK * DD;
    const __half* VHp = VH_g + (size_t)b * TK * DD;

    issue_fill(sb + KBUF(0), sb + VBUF(0), KHp, VHp, tid);
    CP_COMMIT();

    // ---- Q tile gathered through the sort permutation (scale folded)
    const int* permt = PERM_g + b * TQ + qt * BM;
    #pragma unroll
    for (int i = 0; i < 32; i++) {
        int idx = i * THREADS + tid;
        int row = idx >> 5, c4 = (idx & 31) << 2;
        int grow = permt[row];
        float4 v = *(const float4*)(Qg + ((size_t)b * TQ + grow) * DD + c4);
        uint2 wv;
        wv.x = h2bits(v.x * sc, v.y * sc);
        wv.y = h2bits(v.z * sc, v.w * sc);
        *(uint2*)(smem + row * QSTR + c4 * 2) = wv;
    }

    // ---- effective vls + zero-row multiplier (evl==2048 -> s forced to 0 -> p=1)
    int   vl[2][2];
    float zm[2][2];
    #pragma unroll
    for (int g = 0; g < 2; g++)
        #pragma unroll
        for (int h = 0; h < 2; h++) {
            int e = SVL_g[b * TQ + qt * BM + 32 * w + 16 * g + 8 * h + g8];
            vl[g][h] = e;
            zm[g][h] = (e == TK) ? 0.f : 1.f;
        }

    // ---- ldmatrix lane offsets
    const int qrow = (lane & 7) + 8 * ((lane >> 3) & 1);
    const int qcol = 8 * ((lane >> 4) & 1);
    const uint32_t qwb = sb + (32 * w + qrow) * QSTR + qcol * 2;
    const int krow = ((lane >> 4) & 1) * 8 + (lane & 7);
    const int kcol = ((lane >> 3) & 1) * 8;
    const uint32_t ka_off = krow * RSTR + kcol * 2;
    const int vrow = ((lane >> 3) & 1) * 8 + (lane & 7);
    const int vcol = ((lane >> 4) & 1) * 8;
    const uint32_t va_off = vrow * RSTR + vcol * 2;

    float o0[16][4], o1[16][4];
    #pragma unroll
    for (int j = 0; j < 16; j++) {
        o0[j][0] = o0[j][1] = o0[j][2] = o0[j][3] = 0.f;
        o1[j][0] = o1[j][1] = o1[j][2] = o1[j][3] = 0.f;
    }
    float l00 = 0.f, l01 = 0.f, l10 = 0.f, l11 = 0.f;

    for (int c = 0; c < nch; c++) {
        const int cb = c & 1;
        CP_WAIT0();
        __syncthreads();
        if (c + 1 < nch) {
            issue_fill(sb + KBUF(cb ^ 1), sb + VBUF(cb ^ 1),
                       KHp + (size_t)(c + 1) * BN * DD,
                       VHp + (size_t)(c + 1) * BN * DD, tid);
            CP_COMMIT();
        }

        // ---- S = (Q*sc) K^T  [32 rows x 64 keys per warp], K frags shared
        float s0[8][4], s1[8][4];
        #pragma unroll
        for (int j = 0; j < 8; j++) {
            s0[j][0] = s0[j][1] = s0[j][2] = s0[j][3] = 0.f;
            s1[j][0] = s1[j][1] = s1[j][2] = s1[j][3] = 0.f;
        }
        const uint32_t kbase = sb + KBUF(cb) + ka_off;
        #pragma unroll
        for (int kt = 0; kt < 8; kt++) {
            uint32_t qa0[4], qa1[4];
            ldsm4(qa0, qwb + kt * 32);
            ldsm4(qa1, qwb + 16 * QSTR + kt * 32);
            #pragma unroll
            for (int jp = 0; jp < 4; jp++) {
                uint32_t kb[4];
                ldsm4(kb, kbase + jp * (16 * RSTR) + kt * 32);
                mma16816(s0[2 * jp],     qa0, kb[0], kb[1]);
                mma16816(s0[2 * jp + 1], qa0, kb[2], kb[3]);
                mma16816(s1[2 * jp],     qa1, kb[0], kb[1]);
                mma16816(s1[2 * jp + 1], qa1, kb[2], kb[3]);
            }
        }

        // ---- mask + exp (fixed max = 0); zero-rows: s*0 -> p=1
        const int cbase = c * BN + 2 * tig;
        uint32_t p0h[8], p0hh[8], p1h[8], p1hh[8];
        #pragma unroll
        for (int j = 0; j < 8; j++) {
            int cc0 = cbase + 8 * j, cc1 = cc0 + 1;
            float a0 = (cc0 < vl[0][0]) ? __expf(s0[j][0] * zm[0][0]) : 0.f;
            float a1 = (cc1 < vl[0][0]) ? __expf(s0[j][1] * zm[0][0]) : 0.f;
            float a2 = (cc0 < vl[0][1]) ? __expf(s0[j][2] * zm[0][1]) : 0.f;
            float a3 = (cc1 < vl[0][1]) ? __expf(s0[j][3] * zm[0][1]) : 0.f;
            l00 += a0 + a1; l01 += a2 + a3;
            p0h[j]  = h2bits(a0, a1);
            p0hh[j] = h2bits(a2, a3);
            float b0 = (cc0 < vl[1][0]) ? __expf(s1[j][0] * zm[1][0]) : 0.f;
            float b1 = (cc1 < vl[1][0]) ? __expf(s1[j][1] * zm[1][0]) : 0.f;
            float b2 = (cc0 < vl[1][1]) ? __expf(s1[j][2] * zm[1][1]) : 0.f;
            float b3 = (cc1 < vl[1][1]) ? __expf(s1[j][3] * zm[1][1]) : 0.f;
            l10 += b0 + b1; l11 += b2 + b3;
            p1h[j]  = h2bits(b0, b1);
            p1hh[j] = h2bits(b2, b3);
        }

        // ---- O += P V  (V frags shared across both M-groups)
        const uint32_t vbase = sb + VBUF(cb) + va_off;
        #pragma unroll
        for (int kt = 0; kt < 4; kt++) {
            uint32_t a0[4] = { p0h[2 * kt], p0hh[2 * kt], p0h[2 * kt + 1], p0hh[2 * kt + 1] };
            uint32_t a1[4] = { p1h[2 * kt], p1hh[2 * kt], p1h[2 * kt + 1], p1hh[2 * kt + 1] };
            #pragma unroll
            for (int nb = 0; nb < 8; nb++) {
                uint32_t vb[4];
                ldsm4t(vb, vbase + kt * (16 * RSTR) + nb * 32);
                mma16816(o0[2 * nb],     a0, vb[0], vb[1]);
                mma16816(o0[2 * nb + 1], a0, vb[2], vb[3]);
                mma16816(o1[2 * nb],     a1, vb[0], vb[1]);
                mma16816(o1[2 * nb + 1], a1, vb[2], vb[3]);
            }
        }
    }

    // ---- reduce l across the 4 lanes of each row group, write O/l through perm
    l00 += __shfl_xor_sync(0xffffffffu, l00, 1);
    l00 += __shfl_xor_sync(0xffffffffu, l00, 2);
    l01 += __shfl_xor_sync(0xffffffffu, l01, 1);
    l01 += __shfl_xor_sync(0xffffffffu, l01, 2);
    l10 += __shfl_xor_sync(0xffffffffu, l10, 1);
    l10 += __shfl_xor_sync(0xffffffffu, l10, 2);
    l11 += __shfl_xor_sync(0xffffffffu, l11, 1);
    l11 += __shfl_xor_sync(0xffffffffu, l11, 2);
    const float i00 = 1.f / l00, i01 = 1.f / l01;
    const float i10 = 1.f / l10, i11 = 1.f / l11;

    const int rb = b * TQ + qt * BM + 32 * w;
    float* Or00 = Og + ((size_t)b * TQ + PERM_g[rb + g8])      * DD;
    float* Or01 = Og + ((size_t)b * TQ + PERM_g[rb + g8 + 8])  * DD;
    float* Or10 = Og + ((size_t)b * TQ + PERM_g[rb + 16 + g8]) * DD;
    float* Or11 = Og + ((size_t)b * TQ + PERM_g[rb + 24 + g8]) * DD;
    #pragma unroll
    for (int n8 = 0; n8 < 16; n8++) {
        *(float2*)(Or00 + 8 * n8 + 2 * tig) = make_float2(o0[n8][0] * i00, o0[n8][1] * i00);
        *(float2*)(Or01 + 8 * n8 + 2 * tig) = make_float2(o0[n8][2] * i01, o0[n8][3] * i01);
        *(float2*)(Or10 + 8 * n8 + 2 * tig) = make_float2(o1[n8][0] * i10, o1[n8][1] * i10);
        *(float2*)(Or11 + 8 * n8 + 2 * tig) = make_float2(o1[n8][2] * i11, o1[n8][3] * i11);
    }
}

extern "C" void kernel_launch(void* const* d_in, const int* in_sizes, int n_in,
                              void* d_out, int out_size) {
    const float* Q  = (const float*)d_in[0];
    const float* K  = (const float*)d_in[1];
    const float* V  = (const float*)d_in[2];
    const int*   VL = (const int*)d_in[3];

    int vstride = in_sizes[3] / (NB * TQ);   // 1 if int32 words, 2 if int64 words
    if (vstride < 1) vstride = 1;

    sort_vl<<<NB, 256>>>(VL, vstride);
    cvt_kv<<<(KVELEMS / 8 + 255) / 256, 256>>>(K, V);
    sched_k<<<1, NITEM>>>();

    cudaFuncSetAttribute(attn_f16, cudaFuncAttributeMaxDynamicSharedMemorySize, SMEM_TOTAL);
    attn_f16<<<NITEM, THREADS, SMEM_TOTAL>>>(Q, (float*)d_out);
}

// round 14
// speedup vs baseline: 1.8749x; 1.1461x over previous
#include <cuda_runtime.h>
#include <cuda_fp16.h>
#include <cstdint>
#include <math.h>

#define TQ 2048
#define TK 2048
#define DD 128
#define NB 16
#define BM 128
#define BN 64
#define NCH (TK/BN)
#define NTILE (TQ/BM)                  // 16
#define NITEM (NB*NTILE)               // 256
#define THREADS 256                    // 2 warpgroups
#define RSTR 272
#define QSTR 272
#define QBYTES (128*QSTR)              // 34816
#define BUFSZ (64*RSTR)                // 17408
#define KVAREA (4*BUFSZ)               // 69632 per warpgroup (K+V double-buffered)
#define KBUF(wg,i) (QBYTES + (wg)*KVAREA + (i)*2*BUFSZ)
#define VBUF(wg,i) (QBYTES + (wg)*KVAREA + (i)*2*BUFSZ + BUFSZ)
#define SMEM_TOTAL (QBYTES + 2*KVAREA) // 174080 -> 1 CTA/SM
#define DUMPB QBYTES                   // epilogue partial dump (reuses wg0 KV area)
#define DSTR 544                       // 528 payload + pad; 16B-aligned stride

#define KVELEMS (NB*TK*DD)

__device__ __align__(16) __half KH_g[KVELEMS];
__device__ __align__(16) __half VH_g[KVELEMS];
__device__ int PERM_g[NB*TQ];
__device__ int SVL_g[NB*TQ];           // effective vl: 0 -> 2048, else vl
__device__ int SCHED_g[NITEM];

static __device__ __forceinline__ uint32_t smem_u32(const void* p) {
    uint32_t a;
    asm("{ .reg .u64 t; cvta.to.shared.u64 t, %1; cvt.u32.u64 %0, t; }" : "=r"(a) : "l"(p));
    return a;
}
static __device__ __forceinline__ void ldsm4(uint32_t r[4], uint32_t addr) {
    asm volatile("ldmatrix.sync.aligned.m8n8.x4.shared.b16 {%0,%1,%2,%3}, [%4];"
                 : "=r"(r[0]), "=r"(r[1]), "=r"(r[2]), "=r"(r[3]) : "r"(addr));
}
static __device__ __forceinline__ void ldsm4t(uint32_t r[4], uint32_t addr) {
    asm volatile("ldmatrix.sync.aligned.m8n8.x4.trans.shared.b16 {%0,%1,%2,%3}, [%4];"
                 : "=r"(r[0]), "=r"(r[1]), "=r"(r[2]), "=r"(r[3]) : "r"(addr));
}
static __device__ __forceinline__ void mma16816(float c[4], const uint32_t a[4],
                                                uint32_t b0, uint32_t b1) {
    asm volatile(
        "mma.sync.aligned.m16n8k16.row.col.f32.f16.f16.f32 "
        "{%0,%1,%2,%3}, {%4,%5,%6,%7}, {%8,%9}, {%0,%1,%2,%3};"
        : "+f"(c[0]), "+f"(c[1]), "+f"(c[2]), "+f"(c[3])
        : "r"(a[0]), "r"(a[1]), "r"(a[2]), "r"(a[3]), "r"(b0), "r"(b1));
}
static __device__ __forceinline__ uint32_t h2bits(float lo, float hi) {
    __half2 h = __floats2half2_rn(lo, hi);
    return *(uint32_t*)&h;
}
static __device__ __forceinline__ void cp16(uint32_t dst, const void* src) {
    asm volatile("cp.async.cg.shared.global [%0], [%1], 16;" :: "r"(dst), "l"(src) : "memory");
}
#define CP_COMMIT() asm volatile("cp.async.commit_group;" ::: "memory")
#define CP_WAIT0()  asm volatile("cp.async.wait_group 0;" ::: "memory")
#define BAR_WG(id)  asm volatile("bar.sync %0, 128;" :: "r"(id) : "memory")

// ---------------- prepass: fp32 -> fp16 for K and V ----------------
__global__ void __launch_bounds__(256)
cvt_kv(const float* __restrict__ K, const float* __restrict__ V) {
    size_t i = ((size_t)blockIdx.x * 256 + threadIdx.x) * 8;
    if (i >= KVELEMS) return;
    float4 a = *(const float4*)(K + i);
    float4 b = *(const float4*)(K + i + 4);
    uint4 w;
    w.x = h2bits(a.x, a.y); w.y = h2bits(a.z, a.w);
    w.z = h2bits(b.x, b.y); w.w = h2bits(b.z, b.w);
    *(uint4*)(KH_g + i) = w;
    a = *(const float4*)(V + i);
    b = *(const float4*)(V + i + 4);
    w.x = h2bits(a.x, a.y); w.y = h2bits(a.z, a.w);
    w.z = h2bits(b.x, b.y); w.w = h2bits(b.z, b.w);
    *(uint4*)(VH_g + i) = w;
}

// ---------------- prepass: per-batch counting sort of rows by effective vl ----------------
__global__ void __launch_bounds__(256)
sort_vl(const int* __restrict__ VLg, int vstride) {
    __shared__ int hist[TK];
    __shared__ int boff[64];
    const int b = blockIdx.x, tid = threadIdx.x;
    for (int i = tid; i < TK; i += 256) hist[i] = 0;
    __syncthreads();
    for (int r = tid; r < TQ; r += 256) {
        int v = VLg[(size_t)(b * TQ + r) * vstride];
        if (v < 0) v = 0; if (v > TK - 1) v = TK - 1;
        int evl = (v == 0) ? TK : v;
        atomicAdd(&hist[evl - 1], 1);
    }
    __syncthreads();
    if (tid < 64) {
        int s = 0;
        #pragma unroll 4
        for (int i = 0; i < 32; i++) s += hist[tid * 32 + i];
        boff[tid] = s;
    }
    __syncthreads();
    if (tid == 0) {
        int acc = 0;
        for (int i = 0; i < 64; i++) { int t = boff[i]; boff[i] = acc; acc += t; }
    }
    __syncthreads();
    if (tid < 64) {
        int acc = boff[tid];
        #pragma unroll 4
        for (int i = 0; i < 32; i++) {
            int t = hist[tid * 32 + i]; hist[tid * 32 + i] = acc; acc += t;
        }
    }
    __syncthreads();
    for (int r = tid; r < TQ; r += 256) {
        int v = VLg[(size_t)(b * TQ + r) * vstride];
        if (v < 0) v = 0; if (v > TK - 1) v = TK - 1;
        int evl = (v == 0) ? TK : v;
        int pos = atomicAdd(&hist[evl - 1], 1);
        PERM_g[b * TQ + pos] = r;
        SVL_g[b * TQ + pos]  = evl;
    }
}

// ---------------- prepass: schedule heavy tiles first ----------------
__global__ void __launch_bounds__(NITEM)
sched_k() {
    __shared__ int cnt[33];
    const int tid = threadIdx.x;
    if (tid < 33) cnt[tid] = 0;
    __syncthreads();
    const int b = tid >> 4, t = tid & 15;
    const int maxevl = SVL_g[b * TQ + t * BM + BM - 1];
    const int w = (maxevl + 63) >> 6;          // 1..32 chunks
    atomicAdd(&cnt[32 - w], 1);                // key ascending = weight descending
    __syncthreads();
    if (tid == 0) {
        int acc = 0;
        for (int i = 0; i < 33; i++) { int c = cnt[i]; cnt[i] = acc; acc += c; }
    }
    __syncthreads();
    int pos = atomicAdd(&cnt[32 - w], 1);
    SCHED_g[pos] = (b << 4) | t;
}

extern __shared__ char smem[];

static __device__ __forceinline__ void issue_fill(uint32_t sK, uint32_t sV,
                                                  const __half* __restrict__ Ksrc,
                                                  const __half* __restrict__ Vsrc,
                                                  int wtid) {
    #pragma unroll
    for (int i = 0; i < 8; i++) {
        int id  = i * 128 + wtid;
        int row = id >> 4, c16 = (id & 15) << 4;
        cp16(sK + row * RSTR + c16, (const char*)Ksrc + row * 256 + c16);
        cp16(sV + row * RSTR + c16, (const char*)Vsrc + row * 256 + c16);
    }
}

// ---------------- main: one sorted q-tile; 2 warpgroups split the chunk stream ----------------
__global__ void __launch_bounds__(THREADS, 1)
attn_f16(const float* __restrict__ Qg, float* __restrict__ Og)
{
    const int tid  = threadIdx.x;
    const int wg   = tid >> 7;                   // warpgroup 0/1
    const int wtid = tid & 127;
    const int w4   = wtid >> 5, lane = tid & 31;
    const int g8   = lane >> 2;
    const int tig  = lane & 3;
    const int item = SCHED_g[blockIdx.x];
    const int b    = item >> 4, qt = item & 15;
    const float sc = 0.088388347648318447f;      // 1/sqrt(128)

    const int maxevl = SVL_g[b * TQ + qt * BM + BM - 1];
    int nch = (maxevl + 63) >> 6; if (nch > NCH) nch = NCH;

    const uint32_t sb = smem_u32(smem);
    const __half* KHp = KH_g + (size_t)b * TK * DD;
    const __half* VHp = VH_g + (size_t)b * TK * DD;

    // prefill this warpgroup's first chunk (chunk index = wg)
    if (wg < nch)
        issue_fill(sb + KBUF(wg, 0), sb + VBUF(wg, 0),
                   KHp + (size_t)wg * BN * DD, VHp + (size_t)wg * BN * DD, wtid);
    CP_COMMIT();

    // ---- Q tile gathered through the sort permutation (scale folded), 256 threads
    const int* permt = PERM_g + b * TQ + qt * BM;
    #pragma unroll
    for (int i = 0; i < 16; i++) {
        int idx = i * THREADS + tid;
        int row = idx >> 5, c4 = (idx & 31) << 2;
        int grow = permt[row];
        float4 v = *(const float4*)(Qg + ((size_t)b * TQ + grow) * DD + c4);
        uint2 wv;
        wv.x = h2bits(v.x * sc, v.y * sc);
        wv.y = h2bits(v.z * sc, v.w * sc);
        *(uint2*)(smem + row * QSTR + c4 * 2) = wv;
    }

    // ---- effective vls + zero-row multiplier (evl==2048 -> s*0 -> p=1)
    int   vl[2][2];
    float zm[2][2];
    #pragma unroll
    for (int g = 0; g < 2; g++)
        #pragma unroll
        for (int h = 0; h < 2; h++) {
            int e = SVL_g[b * TQ + qt * BM + 32 * w4 + 16 * g + 8 * h + g8];
            vl[g][h] = e;
            zm[g][h] = (e == TK) ? 0.f : 1.f;
        }

    // ---- ldmatrix lane offsets
    const int qrow = (lane & 7) + 8 * ((lane >> 3) & 1);
    const int qcol = 8 * ((lane >> 4) & 1);
    const uint32_t qwb = sb + (32 * w4 + qrow) * QSTR + qcol * 2;
    const int krow = ((lane >> 4) & 1) * 8 + (lane & 7);
    const int kcol = ((lane >> 3) & 1) * 8;
    const uint32_t ka_off = krow * RSTR + kcol * 2;
    const int vrow = ((lane >> 3) & 1) * 8 + (lane & 7);
    const int vcol = ((lane >> 4) & 1) * 8;
    const uint32_t va_off = vrow * RSTR + vcol * 2;

    float o0[16][4], o1[16][4];
    #pragma unroll
    for (int j = 0; j < 16; j++) {
        o0[j][0] = o0[j][1] = o0[j][2] = o0[j][3] = 0.f;
        o1[j][0] = o1[j][1] = o1[j][2] = o1[j][3] = 0.f;
    }
    float l00 = 0.f, l01 = 0.f, l10 = 0.f, l11 = 0.f;

    __syncthreads();                             // Q visible to all warps

    for (int c = wg; c < nch; c += 2) {
        const int cb = (c >> 1) & 1;
        CP_WAIT0();
        BAR_WG(wg + 1);                          // fill(c) visible; compute(c-2) done in wg
        if (c + 2 < nch) {
            issue_fill(sb + KBUF(wg, cb ^ 1), sb + VBUF(wg, cb ^ 1),
                       KHp + (size_t)(c + 2) * BN * DD,
                       VHp + (size_t)(c + 2) * BN * DD, wtid);
            CP_COMMIT();
        }

        // ---- S = (Q*sc) K^T  [32 rows x 64 keys per warp], K frags shared
        float s0[8][4], s1[8][4];
        #pragma unroll
        for (int j = 0; j < 8; j++) {
            s0[j][0] = s0[j][1] = s0[j][2] = s0[j][3] = 0.f;
            s1[j][0] = s1[j][1] = s1[j][2] = s1[j][3] = 0.f;
        }
        const uint32_t kbase = sb + KBUF(wg, cb) + ka_off;
        #pragma unroll
        for (int kt = 0; kt < 8; kt++) {
            uint32_t qa0[4], qa1[4];
            ldsm4(qa0, qwb + kt * 32);
            ldsm4(qa1, qwb + 16 * QSTR + kt * 32);
            #pragma unroll
            for (int jp = 0; jp < 4; jp++) {
                uint32_t kb[4];
                ldsm4(kb, kbase + jp * (16 * RSTR) + kt * 32);
                mma16816(s0[2 * jp],     qa0, kb[0], kb[1]);
                mma16816(s0[2 * jp + 1], qa0, kb[2], kb[3]);
                mma16816(s1[2 * jp],     qa1, kb[0], kb[1]);
                mma16816(s1[2 * jp + 1], qa1, kb[2], kb[3]);
            }
        }

        // ---- mask + exp (fixed max = 0); zero-rows: s*0 -> p=1
        const int cbase = c * BN + 2 * tig;
        uint32_t p0h[8], p0hh[8], p1h[8], p1hh[8];
        #pragma unroll
        for (int j = 0; j < 8; j++) {
            int cc0 = cbase + 8 * j, cc1 = cc0 + 1;
            float a0 = (cc0 < vl[0][0]) ? __expf(s0[j][0] * zm[0][0]) : 0.f;
            float a1 = (cc1 < vl[0][0]) ? __expf(s0[j][1] * zm[0][0]) : 0.f;
            float a2 = (cc0 < vl[0][1]) ? __expf(s0[j][2] * zm[0][1]) : 0.f;
            float a3 = (cc1 < vl[0][1]) ? __expf(s0[j][3] * zm[0][1]) : 0.f;
            l00 += a0 + a1; l01 += a2 + a3;
            p0h[j]  = h2bits(a0, a1);
            p0hh[j] = h2bits(a2, a3);
            float b0 = (cc0 < vl[1][0]) ? __expf(s1[j][0] * zm[1][0]) : 0.f;
            float b1 = (cc1 < vl[1][0]) ? __expf(s1[j][1] * zm[1][0]) : 0.f;
            float b2 = (cc0 < vl[1][1]) ? __expf(s1[j][2] * zm[1][1]) : 0.f;
            float b3 = (cc1 < vl[1][1]) ? __expf(s1[j][3] * zm[1][1]) : 0.f;
            l10 += b0 + b1; l11 += b2 + b3;
            p1h[j]  = h2bits(b0, b1);
            p1hh[j] = h2bits(b2, b3);
        }

        // ---- O += P V  (V frags shared across both M-groups)
        const uint32_t vbase = sb + VBUF(wg, cb) + va_off;
        #pragma unroll
        for (int kt = 0; kt < 4; kt++) {
            uint32_t a0[4] = { p0h[2 * kt], p0hh[2 * kt], p0h[2 * kt + 1], p0hh[2 * kt + 1] };
            uint32_t a1[4] = { p1h[2 * kt], p1hh[2 * kt], p1h[2 * kt + 1], p1hh[2 * kt + 1] };
            #pragma unroll
            for (int nb = 0; nb < 8; nb++) {
                uint32_t vb[4];
                ldsm4t(vb, vbase + kt * (16 * RSTR) + nb * 32);
                mma16816(o0[2 * nb],     a0, vb[0], vb[1]);
                mma16816(o0[2 * nb + 1], a0, vb[2], vb[3]);
                mma16816(o1[2 * nb],     a1, vb[0], vb[1]);
                mma16816(o1[2 * nb + 1], a1, vb[2], vb[3]);
            }
        }
    }

    // ---- combine warpgroup partials: wg1 dumps to smem, wg0 adds & writes
    __syncthreads();
    char* dp = smem + DUMPB + wtid * DSTR;
    if (wg == 1) {
        #pragma unroll
        for (int n8 = 0; n8 < 16; n8++) {
            *(float2*)(dp + n8 * 16)       = make_float2(o0[n8][0], o0[n8][1]);
            *(float2*)(dp + n8 * 16 + 8)   = make_float2(o0[n8][2], o0[n8][3]);
            *(float2*)(dp + 256 + n8 * 16)     = make_float2(o1[n8][0], o1[n8][1]);
            *(float2*)(dp + 256 + n8 * 16 + 8) = make_float2(o1[n8][2], o1[n8][3]);
        }
        *(float4*)(dp + 512) = make_float4(l00, l01, l10, l11);
    }
    __syncthreads();
    if (wg == 0) {
        #pragma unroll
        for (int n8 = 0; n8 < 16; n8++) {
            float2 v;
            v = *(float2*)(dp + n8 * 16);           o0[n8][0] += v.x; o0[n8][1] += v.y;
            v = *(float2*)(dp + n8 * 16 + 8);       o0[n8][2] += v.x; o0[n8][3] += v.y;
            v = *(float2*)(dp + 256 + n8 * 16);     o1[n8][0] += v.x; o1[n8][1] += v.y;
            v = *(float2*)(dp + 256 + n8 * 16 + 8); o1[n8][2] += v.x; o1[n8][3] += v.y;
        }
        float4 lv = *(float4*)(dp + 512);
        l00 += lv.x; l01 += lv.y; l10 += lv.z; l11 += lv.w;

        l00 += __shfl_xor_sync(0xffffffffu, l00, 1);
        l00 += __shfl_xor_sync(0xffffffffu, l00, 2);
        l01 += __shfl_xor_sync(0xffffffffu, l01, 1);
        l01 += __shfl_xor_sync(0xffffffffu, l01, 2);
        l10 += __shfl_xor_sync(0xffffffffu, l10, 1);
        l10 += __shfl_xor_sync(0xffffffffu, l10, 2);
        l11 += __shfl_xor_sync(0xffffffffu, l11, 1);
        l11 += __shfl_xor_sync(0xffffffffu, l11, 2);
        const float i00 = 1.f / l00, i01 = 1.f / l01;
        const float i10 = 1.f / l10, i11 = 1.f / l11;

        const int rb = b * TQ + qt * BM + 32 * w4;
        float* Or00 = Og + ((size_t)b * TQ + PERM_g[rb + g8])      * DD;
        float* Or01 = Og + ((size_t)b * TQ + PERM_g[rb + g8 + 8])  * DD;
        float* Or10 = Og + ((size_t)b * TQ + PERM_g[rb + 16 + g8]) * DD;
        float* Or11 = Og + ((size_t)b * TQ + PERM_g[rb + 24 + g8]) * DD;
        #pragma unroll
        for (int n8 = 0; n8 < 16; n8++) {
            *(float2*)(Or00 + 8 * n8 + 2 * tig) = make_float2(o0[n8][0] * i00, o0[n8][1] * i00);
            *(float2*)(Or01 + 8 * n8 + 2 * tig) = make_float2(o0[n8][2] * i01, o0[n8][3] * i01);
            *(float2*)(Or10 + 8 * n8 + 2 * tig) = make_float2(o1[n8][0] * i10, o1[n8][1] * i10);
            *(float2*)(Or11 + 8 * n8 + 2 * tig) = make_float2(o1[n8][2] * i11, o1[n8][3] * i11);
        }
    }
}

extern "C" void kernel_launch(void* const* d_in, const int* in_sizes, int n_in,
                              void* d_out, int out_size) {
    const float* Q  = (const float*)d_in[0];
    const float* K  = (const float*)d_in[1];
    const float* V  = (const float*)d_in[2];
    const int*   VL = (const int*)d_in[3];

    int vstride = in_sizes[3] / (NB * TQ);   // 1 if int32 words, 2 if int64 words
    if (vstride < 1) vstride = 1;

    sort_vl<<<NB, 256>>>(VL, vstride);
    cvt_kv<<<(KVELEMS / 8 + 255) / 256, 256>>>(K, V);
    sched_k<<<1, NITEM>>>();

    cudaFuncSetAttribute(attn_f16, cudaFuncAttributeMaxDynamicSharedMemorySize, SMEM_TOTAL);
    attn_f16<<<NITEM, THREADS, SMEM_TOTAL>>>(Q, (float*)d_out);
}